// round 15
// baseline (speedup 1.0000x reference)
#include <cuda_runtime.h>
#include <cstdint>
#include <cstddef>

#define D 128
#define NMAX 100000

// ---------------- static device scratch (no dynamic allocs allowed) -------
__device__ float g_agg[(size_t)NMAX * D];
__device__ float g_agg2[(size_t)NMAX * D];
__device__ float g_h[(size_t)NMAX * D];
__device__ float g_deg[NMAX];

#define RSTR 544                       // bytes per 256-k bf16 row (512 + 32 pad)
__device__ __align__(16) char g_wt[2][128 * RSTR];   // layer1: W1^T|Wl1^T, layer2: W2^T|Wl2^T

// ---------------- helpers -------------------------------------------------
__device__ __forceinline__ void red4(float* p, float4 v) {
    asm volatile("red.global.add.v4.f32 [%0], {%1,%2,%3,%4};"
                 :: "l"(p), "f"(v.x), "f"(v.y), "f"(v.z), "f"(v.w) : "memory");
}

__device__ __forceinline__ float tanh_fast(float x) {
    float y;
    asm("tanh.approx.f32 %0, %1;" : "=f"(y) : "f"(x));
    return y;
}

__device__ __forceinline__ uint32_t bf16x2(float lo, float hi) {
    uint32_t r;
    asm("cvt.rn.bf16x2.f32 %0, %1, %2;" : "=r"(r) : "f"(hi), "f"(lo));
    return r;
}

__device__ __forceinline__ void mma_bf16(float* c,
                                         uint32_t a0, uint32_t a1,
                                         uint32_t a2, uint32_t a3,
                                         uint32_t b0, uint32_t b1) {
    asm("mma.sync.aligned.m16n8k16.row.col.f32.bf16.bf16.f32 "
        "{%0,%1,%2,%3}, {%4,%5,%6,%7}, {%8,%9}, {%0,%1,%2,%3};"
        : "+f"(c[0]), "+f"(c[1]), "+f"(c[2]), "+f"(c[3])
        : "r"(a0), "r"(a1), "r"(a2), "r"(a3), "r"(b0), "r"(b1));
}

// Permuted-k bf16 quad store; valid for k % 4 == 0, k in [0, 256).
__device__ __forceinline__ void store_bf16_quad(char* rowbase, int k, float4 v) {
    char* p = rowbase + ((k >> 4) * 32) + (((k & 7) >> 1) * 8) + (((k >> 3) & 1) * 4);
    *(uint32_t*)p       = bf16x2(v.x, v.y);
    *(uint32_t*)(p + 8) = bf16x2(v.z, v.w);
}
// same layout, raw pre-packed bf16x2 pair {k,k+1},{k+2,k+3}
__device__ __forceinline__ void store_bf16_quad_raw(char* rowbase, int k, uint2 u) {
    char* p = rowbase + ((k >> 4) * 32) + (((k & 7) >> 1) * 8) + (((k >> 3) & 1) * 4);
    *(uint32_t*)p       = u.x;
    *(uint32_t*)(p + 8) = u.y;
}

// ---------------- prep: both layer weight pairs -> perm-k bf16 (once) -----
__global__ void prep_weights_kernel(const float* __restrict__ W1,
                                    const float* __restrict__ Wl1,
                                    const float* __restrict__ W2,
                                    const float* __restrict__ Wl2)
{
    const float* w  = blockIdx.x ? W2  : W1;
    const float* wl = blockIdx.x ? Wl2 : Wl1;
    const int n = threadIdx.x;
    char* brow = g_wt[blockIdx.x] + n * RSTR;
    #pragma unroll 4
    for (int k = 0; k < 128; k += 4) {
        float4 a, b;
        a.x = __ldg(w  + (k + 0) * 128 + n);
        a.y = __ldg(w  + (k + 1) * 128 + n);
        a.z = __ldg(w  + (k + 2) * 128 + n);
        a.w = __ldg(w  + (k + 3) * 128 + n);
        b.x = __ldg(wl + (k + 0) * 128 + n);
        b.y = __ldg(wl + (k + 1) * 128 + n);
        b.z = __ldg(wl + (k + 2) * 128 + n);
        b.w = __ldg(wl + (k + 3) * 128 + n);
        store_bf16_quad(brow, k, a);
        store_bf16_quad(brow, k + 128, b);
    }
}

// ---------------- invdeg: deg <- 1/max(deg,1) in place --------------------
__global__ void invdeg_kernel(float* __restrict__ deg, int N) {
    int i = blockIdx.x * blockDim.x + threadIdx.x;
    if (i < N) deg[i] = 1.0f / fmaxf(deg[i], 1.0f);
}

// ---------------- scatter: 4 edges per warp (4 independent chains) --------
__global__ void scatter_kernel(const float* __restrict__ x,
                               const float* __restrict__ rel,
                               const int* __restrict__ ei,     // [2, E]
                               const int* __restrict__ etype,  // [E]
                               float* __restrict__ agg,
                               float* __restrict__ deg,        // null on layer 2
                               int E)
{
    int w = blockIdx.x * (blockDim.x >> 5) + (threadIdx.x >> 5);
    int e0 = w * 4;
    if (e0 >= E) return;
    int lane = threadIdx.x & 31;

    int s[4], d[4], tt[4];
    bool has[4];
    #pragma unroll
    for (int i = 0; i < 4; i++) {
        int e = e0 + i;
        has[i] = e < E;
        s[i]  = has[i] ? __ldg(ei + e) : 0;
        d[i]  = has[i] ? __ldg(ei + E + e) : 0;
        tt[i] = has[i] ? __ldg(etype + e) : 0;
    }

    float4 xv[4], rv[4];
    #pragma unroll
    for (int i = 0; i < 4; i++) {
        xv[i] = has[i] ? *(const float4*)(x + (size_t)s[i] * D + lane * 4)
                       : make_float4(0.f, 0.f, 0.f, 0.f);
        rv[i] = has[i] ? *(const float4*)(rel + (size_t)tt[i] * D + lane * 4)
                       : make_float4(0.f, 0.f, 0.f, 0.f);
    }

    #pragma unroll
    for (int i = 0; i < 4; i++) {
        if (!has[i]) break;
        float4 m;
        m.x = xv[i].x * rv[i].x; m.y = xv[i].y * rv[i].y;
        m.z = xv[i].z * rv[i].z; m.w = xv[i].w * rv[i].w;
        red4(agg + (size_t)d[i] * D + lane * 4, m);
    }
    if (deg != nullptr && lane == 0) {
        #pragma unroll
        for (int i = 0; i < 4; i++)
            if (has[i]) atomicAdd(deg + d[i], 1.0f);
    }
}

// ---------------- jump: 4 edges per warp ----------------------------------
__global__ void jump_kernel(const float* __restrict__ emb,
                            const float* __restrict__ ew,
                            const int* __restrict__ ej,   // [2, EJ]
                            const float* __restrict__ jw_p,
                            float* __restrict__ out,
                            int EJ)
{
    int w = blockIdx.x * (blockDim.x >> 5) + (threadIdx.x >> 5);
    int e0 = w * 4;
    if (e0 >= EJ) return;
    int lane = threadIdx.x & 31;
    const float jwv = __ldg(jw_p);

    int s[4], d[4];
    float wt[4];
    bool has[4];
    #pragma unroll
    for (int i = 0; i < 4; i++) {
        int e = e0 + i;
        has[i] = e < EJ;
        s[i]  = has[i] ? __ldg(ej + e) : 0;
        d[i]  = has[i] ? __ldg(ej + EJ + e) : 0;
        wt[i] = has[i] ? __ldg(ew + e) * jwv : 0.0f;
    }

    float4 xv[4];
    #pragma unroll
    for (int i = 0; i < 4; i++)
        xv[i] = has[i] ? *(const float4*)(emb + (size_t)s[i] * D + lane * 4)
                       : make_float4(0.f, 0.f, 0.f, 0.f);

    #pragma unroll
    for (int i = 0; i < 4; i++) {
        if (!has[i]) break;
        float4 m;
        m.x = xv[i].x * wt[i]; m.y = xv[i].y * wt[i];
        m.z = xv[i].z * wt[i]; m.w = xv[i].w * wt[i];
        red4(out + (size_t)d[i] * D + lane * 4, m);
    }
}

// ---------------- pipelined tensor-core GEMM (virtual K=256) --------------
// out[r] = xb[r] + res * tanh( agg[r]*invdeg[r] @ W + xb[r] @ Wl )
// M_TILE=128, warp tile 32x32 (16 warps = 4m x 4n) -> LDS:mma = 1.0.
// Staging converts to bf16 in registers (16 uint2), double-buffered A.
#define NT 512
#define ASZ (128 * RSTR)                   // 69632
#define GEMM_SMEM (3 * ASZ)                // 208896 B, 1 CTA/SM

__global__ __launch_bounds__(NT, 1)
void gemm_mma_kernel(const float* __restrict__ agg,
                     const float* __restrict__ invdeg,
                     const float* __restrict__ xb,
                     const char* __restrict__ wt,     // prepped [128][RSTR]
                     const float* __restrict__ res_p,
                     float* __restrict__ out,
                     int N)
{
    extern __shared__ char smem[];
    char* Bs = smem + 2 * ASZ;

    const int t    = threadIdx.x;
    const int lane = t & 31;
    const int wid  = t >> 5;
    const int warp_m = wid & 3;      // 4 groups x 32 rows
    const int warp_n = wid >> 2;     // 4 groups x 32 cols

    // stage full B (both weights) once
    for (int i = t * 16; i < 128 * RSTR; i += NT * 16)
        *(uint4*)(Bs + i) = *(const uint4*)(wt + i);
    const float res = __ldg(res_p);

    // per-thread staging geometry: fixed kv column, rows m0+8s (s=0..15)
    const int kvt = (t * 4) & 255;
    const int m0  = (t * 4) >> 8;            // 0..7
    const bool isagg = kvt < 128;
    const float* asrc = isagg ? agg : xb;
    const int koff = isagg ? kvt : kvt - 128;

    const int a_base = (warp_m * 32 + (lane >> 2)) * RSTR + (lane & 3) * 8;
    const int b_base = (warp_n * 32 + (lane >> 2)) * RSTR + (lane & 3) * 8;

    const int tile_step = gridDim.x * 128;
    int row0 = blockIdx.x * 128;
    if (row0 >= N) return;

    uint2 rq[16];   // staged bf16 quads (packed at load time)

    // load+pack helper pattern (inlined twice)
    #define LOAD_TILE(base)                                                   \
        _Pragma("unroll")                                                     \
        for (int s = 0; s < 16; s++) {                                        \
            int row = (base) + m0 + 8 * s;                                    \
            float4 v = make_float4(0.f, 0.f, 0.f, 0.f);                       \
            if (row < N) {                                                    \
                v = *(const float4*)(asrc + (size_t)row * D + koff);          \
                if (isagg) {                                                  \
                    float sc = __ldg(invdeg + row);                           \
                    v.x *= sc; v.y *= sc; v.z *= sc; v.w *= sc;               \
                }                                                             \
            }                                                                 \
            rq[s].x = bf16x2(v.x, v.y);                                       \
            rq[s].y = bf16x2(v.z, v.w);                                       \
        }

    #define STORE_TILE(Ab)                                                    \
        _Pragma("unroll")                                                     \
        for (int s = 0; s < 16; s++)                                          \
            store_bf16_quad_raw((Ab) + (m0 + 8 * s) * RSTR, kvt, rq[s]);

    // prologue: tile 0 -> buffer 0
    LOAD_TILE(row0)
    STORE_TILE(smem)

    int buf = 0;
    for (; row0 < N; ) {
        const int next = row0 + tile_step;
        const bool havenext = next < N;

        if (havenext) { LOAD_TILE(next) }

        __syncthreads();
        const char* Ab = smem + buf * ASZ;

        float acc[2][4][4];
        #pragma unroll
        for (int mf = 0; mf < 2; mf++)
            #pragma unroll
            for (int nf = 0; nf < 4; nf++)
                #pragma unroll
                for (int j = 0; j < 4; j++) acc[mf][nf][j] = 0.0f;

        #pragma unroll
        for (int ks = 0; ks < 16; ks++) {
            uint2 af[2][2];
            #pragma unroll
            for (int mf = 0; mf < 2; mf++) {
                const char* ap = Ab + a_base + mf * 16 * RSTR + ks * 32;
                af[mf][0] = *(const uint2*)ap;
                af[mf][1] = *(const uint2*)(ap + 8 * RSTR);
            }
            #pragma unroll
            for (int nf = 0; nf < 4; nf++) {
                uint2 b = *(const uint2*)(Bs + b_base + nf * 8 * RSTR + ks * 32);
                mma_bf16(acc[0][nf], af[0][0].x, af[0][1].x, af[0][0].y, af[0][1].y, b.x, b.y);
                mma_bf16(acc[1][nf], af[1][0].x, af[1][1].x, af[1][0].y, af[1][1].y, b.x, b.y);
            }
        }

        // epilogue: res*tanh + fp32 residual
        #pragma unroll
        for (int mf = 0; mf < 2; mf++) {
            #pragma unroll
            for (int half = 0; half < 2; half++) {
                int row = row0 + warp_m * 32 + mf * 16 + half * 8 + (lane >> 2);
                if (row < N) {
                    #pragma unroll
                    for (int nf = 0; nf < 4; nf++) {
                        int col = warp_n * 32 + nf * 8 + 2 * (lane & 3);
                        float v0 = acc[mf][nf][half * 2 + 0];
                        float v1 = acc[mf][nf][half * 2 + 1];
                        float2 b = *(const float2*)(xb + (size_t)row * D + col);
                        float2 o;
                        o.x = b.x + res * tanh_fast(v0);
                        o.y = b.y + res * tanh_fast(v1);
                        *(float2*)(out + (size_t)row * D + col) = o;
                    }
                }
            }
        }

        if (havenext) {
            char* An = smem + (buf ^ 1) * ASZ;
            STORE_TILE(An)
        }
        buf ^= 1;
        row0 = next;
    }
    #undef LOAD_TILE
    #undef STORE_TILE
}

// ---------------- launcher ------------------------------------------------
extern "C" void kernel_launch(void* const* d_in, const int* in_sizes, int n_in,
                              void* d_out, int out_size)
{
    const float* emb    = (const float*)d_in[0];
    const float* change = (const float*)d_in[1];
    const float* W1     = (const float*)d_in[2];
    const float* Wl1    = (const float*)d_in[3];
    const float* rel1   = (const float*)d_in[4];
    const float* W2     = (const float*)d_in[5];
    const float* Wl2    = (const float*)d_in[6];
    const float* rel2   = (const float*)d_in[7];
    const float* res    = (const float*)d_in[8];
    const float* jw     = (const float*)d_in[9];
    const float* ewj    = (const float*)d_in[10];
    const int*   ei     = (const int*)d_in[11];
    const int*   et     = (const int*)d_in[12];
    const int*   ej     = (const int*)d_in[13];

    const int N  = in_sizes[0] / D;
    const int E  = in_sizes[12];
    const int EJ = in_sizes[10];

    float* out = (float*)d_out;

    float *agg, *agg2, *h, *deg;
    char* wt;
    cudaGetSymbolAddress((void**)&agg,  g_agg);
    cudaGetSymbolAddress((void**)&agg2, g_agg2);
    cudaGetSymbolAddress((void**)&h,    g_h);
    cudaGetSymbolAddress((void**)&deg,  g_deg);
    cudaGetSymbolAddress((void**)&wt,   g_wt);

    cudaFuncSetAttribute(gemm_mma_kernel,
                         cudaFuncAttributeMaxDynamicSharedMemorySize, GEMM_SMEM);

    const size_t nd = (size_t)N * D * sizeof(float);

    prep_weights_kernel<<<2, 128>>>(W1, Wl1, W2, Wl2);
    cudaMemsetAsync(agg,  0, nd);
    cudaMemsetAsync(agg2, 0, nd);
    cudaMemsetAsync(deg,  0, (size_t)N * sizeof(float));
    cudaMemcpyAsync(out, change, nd, cudaMemcpyDeviceToDevice);

    const int eb = ((E + 3) / 4 + 7) / 8;      // 4 edges per warp, 8 warps/block
    const int jb = ((EJ + 3) / 4 + 7) / 8;

    scatter_kernel<<<eb, 256>>>(emb, rel1, ei, et, agg, deg, E);
    invdeg_kernel<<<(N + 1023) / 1024, 1024>>>(deg, N);

    gemm_mma_kernel<<<148, NT, GEMM_SMEM>>>(
        agg, deg, emb, wt + 0 * 128 * RSTR, res, h, N);

    scatter_kernel<<<eb, 256>>>(h, rel2, ei, et, agg2, nullptr, E);

    gemm_mma_kernel<<<148, NT, GEMM_SMEM>>>(
        agg2, deg, h, wt + 1 * 128 * RSTR, res, out + (size_t)N * D, N);

    jump_kernel<<<jb, 256>>>(emb, ewj, ej, jw, out + (size_t)N * D, EJ);
}

// round 16
// speedup vs baseline: 1.0670x; 1.0670x over previous
#include <cuda_runtime.h>
#include <cstdint>
#include <cstddef>

#define D 128
#define NMAX 100000

// ---------------- static device scratch (no dynamic allocs allowed) -------
__device__ float g_agg[(size_t)NMAX * D];
__device__ float g_agg2[(size_t)NMAX * D];
__device__ float g_h[(size_t)NMAX * D];
__device__ float g_deg[NMAX];

#define RSTR 544                       // bytes per 256-k bf16 row (512 + 32 pad)
__device__ __align__(16) char g_wt[2][128 * RSTR];   // layer1: W1^T|Wl1^T, layer2: W2^T|Wl2^T

// ---------------- helpers -------------------------------------------------
__device__ __forceinline__ void red4(float* p, float4 v) {
    asm volatile("red.global.add.v4.f32 [%0], {%1,%2,%3,%4};"
                 :: "l"(p), "f"(v.x), "f"(v.y), "f"(v.z), "f"(v.w) : "memory");
}

__device__ __forceinline__ float tanh_fast(float x) {
    float y;
    asm("tanh.approx.f32 %0, %1;" : "=f"(y) : "f"(x));
    return y;
}

__device__ __forceinline__ uint32_t bf16x2(float lo, float hi) {
    uint32_t r;
    asm("cvt.rn.bf16x2.f32 %0, %1, %2;" : "=r"(r) : "f"(hi), "f"(lo));
    return r;
}

__device__ __forceinline__ void mma_bf16(float* c,
                                         uint32_t a0, uint32_t a1,
                                         uint32_t a2, uint32_t a3,
                                         uint32_t b0, uint32_t b1) {
    asm("mma.sync.aligned.m16n8k16.row.col.f32.bf16.bf16.f32 "
        "{%0,%1,%2,%3}, {%4,%5,%6,%7}, {%8,%9}, {%0,%1,%2,%3};"
        : "+f"(c[0]), "+f"(c[1]), "+f"(c[2]), "+f"(c[3])
        : "r"(a0), "r"(a1), "r"(a2), "r"(a3), "r"(b0), "r"(b1));
}

// Permuted-k bf16 quad store; valid for k % 4 == 0, k in [0, 256).
__device__ __forceinline__ void store_bf16_quad(char* rowbase, int k, float4 v) {
    char* p = rowbase + ((k >> 4) * 32) + (((k & 7) >> 1) * 8) + (((k >> 3) & 1) * 4);
    *(uint32_t*)p       = bf16x2(v.x, v.y);
    *(uint32_t*)(p + 8) = bf16x2(v.z, v.w);
}

// ---------------- prep: both layer weight pairs -> perm-k bf16 (once) -----
__global__ void prep_weights_kernel(const float* __restrict__ W1,
                                    const float* __restrict__ Wl1,
                                    const float* __restrict__ W2,
                                    const float* __restrict__ Wl2)
{
    const float* w  = blockIdx.x ? W2  : W1;
    const float* wl = blockIdx.x ? Wl2 : Wl1;
    const int n = threadIdx.x;
    char* brow = g_wt[blockIdx.x] + n * RSTR;
    #pragma unroll 4
    for (int k = 0; k < 128; k += 4) {
        float4 a, b;
        a.x = __ldg(w  + (k + 0) * 128 + n);
        a.y = __ldg(w  + (k + 1) * 128 + n);
        a.z = __ldg(w  + (k + 2) * 128 + n);
        a.w = __ldg(w  + (k + 3) * 128 + n);
        b.x = __ldg(wl + (k + 0) * 128 + n);
        b.y = __ldg(wl + (k + 1) * 128 + n);
        b.z = __ldg(wl + (k + 2) * 128 + n);
        b.w = __ldg(wl + (k + 3) * 128 + n);
        store_bf16_quad(brow, k, a);
        store_bf16_quad(brow, k + 128, b);
    }
}

// ---------------- scatter: 4 edges per warp (4 independent chains) --------
// agg[dst] += x[src] * rel[etype]; deg count on layer 1.
__global__ void scatter_kernel(const float* __restrict__ x,
                               const float* __restrict__ rel,
                               const int* __restrict__ ei,     // [2, E]
                               const int* __restrict__ etype,  // [E]
                               float* __restrict__ agg,
                               float* __restrict__ deg,        // null on layer 2
                               int E)
{
    int w = blockIdx.x * (blockDim.x >> 5) + (threadIdx.x >> 5);
    int e0 = w * 4;
    if (e0 >= E) return;
    int lane = threadIdx.x & 31;

    int s[4], d[4], tt[4];
    bool has[4];
    #pragma unroll
    for (int i = 0; i < 4; i++) {
        int e = e0 + i;
        has[i] = e < E;
        s[i]  = has[i] ? __ldg(ei + e) : 0;
        d[i]  = has[i] ? __ldg(ei + E + e) : 0;
        tt[i] = has[i] ? __ldg(etype + e) : 0;
    }

    // 8 independent gather chains in flight
    float4 xv[4], rv[4];
    #pragma unroll
    for (int i = 0; i < 4; i++) {
        xv[i] = has[i] ? *(const float4*)(x + (size_t)s[i] * D + lane * 4)
                       : make_float4(0.f, 0.f, 0.f, 0.f);
        rv[i] = has[i] ? *(const float4*)(rel + (size_t)tt[i] * D + lane * 4)
                       : make_float4(0.f, 0.f, 0.f, 0.f);
    }

    #pragma unroll
    for (int i = 0; i < 4; i++) {
        if (!has[i]) break;
        float4 m;
        m.x = xv[i].x * rv[i].x; m.y = xv[i].y * rv[i].y;
        m.z = xv[i].z * rv[i].z; m.w = xv[i].w * rv[i].w;
        red4(agg + (size_t)d[i] * D + lane * 4, m);
    }
    if (deg != nullptr && lane == 0) {
        #pragma unroll
        for (int i = 0; i < 4; i++)
            if (has[i]) atomicAdd(deg + d[i], 1.0f);
    }
}

// ---------------- jump: 4 edges per warp ----------------------------------
__global__ void jump_kernel(const float* __restrict__ emb,
                            const float* __restrict__ ew,
                            const int* __restrict__ ej,   // [2, EJ]
                            const float* __restrict__ jw_p,
                            float* __restrict__ out,
                            int EJ)
{
    int w = blockIdx.x * (blockDim.x >> 5) + (threadIdx.x >> 5);
    int e0 = w * 4;
    if (e0 >= EJ) return;
    int lane = threadIdx.x & 31;
    const float jwv = __ldg(jw_p);

    int s[4], d[4];
    float wt[4];
    bool has[4];
    #pragma unroll
    for (int i = 0; i < 4; i++) {
        int e = e0 + i;
        has[i] = e < EJ;
        s[i]  = has[i] ? __ldg(ej + e) : 0;
        d[i]  = has[i] ? __ldg(ej + EJ + e) : 0;
        wt[i] = has[i] ? __ldg(ew + e) * jwv : 0.0f;
    }

    float4 xv[4];
    #pragma unroll
    for (int i = 0; i < 4; i++)
        xv[i] = has[i] ? *(const float4*)(emb + (size_t)s[i] * D + lane * 4)
                       : make_float4(0.f, 0.f, 0.f, 0.f);

    #pragma unroll
    for (int i = 0; i < 4; i++) {
        if (!has[i]) break;
        float4 m;
        m.x = xv[i].x * wt[i]; m.y = xv[i].y * wt[i];
        m.z = xv[i].z * wt[i]; m.w = xv[i].w * wt[i];
        red4(out + (size_t)d[i] * D + lane * 4, m);
    }
}

// ---------------- pipelined tensor-core GEMM (virtual K=256) --------------
// out[r] = xb[r] + res * tanh( agg[r]/max(deg[r],1) @ W + xb[r] @ Wl )
// 512 threads, 1 CTA/SM; 64-row tiles; double-buffered A; deg inverted
// inline during staging (no separate invdeg kernel).
#define NT 512
#define ASZ (64 * RSTR)                    // 34816
#define GEMM_SMEM (2 * ASZ + 128 * RSTR)   // 139264 B

__global__ __launch_bounds__(NT, 1)
void gemm_mma_kernel(const float* __restrict__ agg,
                     const float* __restrict__ deg,
                     const float* __restrict__ xb,
                     const char* __restrict__ wt,     // prepped [128][RSTR]
                     const float* __restrict__ res_p,
                     float* __restrict__ out,
                     int N)
{
    extern __shared__ char smem[];
    char* Bs = smem + 2 * ASZ;

    const int t    = threadIdx.x;
    const int lane = t & 31;
    const int wid  = t >> 5;
    const int warp_m = wid & 3;      // 4 groups x 16 rows
    const int warp_n = wid >> 2;     // 4 groups x 32 cols

    for (int i = t * 16; i < 128 * RSTR; i += NT * 16)
        *(uint4*)(Bs + i) = *(const uint4*)(wt + i);
    const float res = __ldg(res_p);

    const int kvt = (t * 4) & 255;
    const int m0  = (t * 4) >> 8;            // 0..7
    const bool isagg = kvt < 128;
    const float* asrc = isagg ? agg : xb;
    const int koff = isagg ? kvt : kvt - 128;

    const int a_base = (warp_m * 16 + (lane >> 2)) * RSTR + (lane & 3) * 8;
    const int b_base = (warp_n * 32 + (lane >> 2)) * RSTR + (lane & 3) * 8;

    const int tile_step = gridDim.x * 64;
    int row0 = blockIdx.x * 64;
    if (row0 >= N) return;

    float4 r[8];
    float  dv[8];

    // prologue: load + store tile 0 into buffer 0
    #pragma unroll
    for (int s = 0; s < 8; s++) {
        int row = row0 + m0 + 8 * s;
        if (row < N) {
            r[s] = *(const float4*)(asrc + (size_t)row * D + koff);
            dv[s] = isagg ? (1.0f / fmaxf(__ldg(deg + row), 1.0f)) : 1.0f;
        } else {
            r[s] = make_float4(0.f, 0.f, 0.f, 0.f);
            dv[s] = 1.0f;
        }
    }
    {
        char* Ab = smem;
        #pragma unroll
        for (int s = 0; s < 8; s++) {
            float4 v = r[s];
            v.x *= dv[s]; v.y *= dv[s]; v.z *= dv[s]; v.w *= dv[s];
            store_bf16_quad(Ab + (m0 + 8 * s) * RSTR, kvt, v);
        }
    }

    int buf = 0;
    for (; row0 < N; ) {
        const int next = row0 + tile_step;
        const bool havenext = next < N;

        // issue next tile's global loads (latency hidden behind mma below)
        if (havenext) {
            #pragma unroll
            for (int s = 0; s < 8; s++) {
                int row = next + m0 + 8 * s;
                if (row < N) {
                    r[s] = *(const float4*)(asrc + (size_t)row * D + koff);
                    dv[s] = isagg ? (1.0f / fmaxf(__ldg(deg + row), 1.0f)) : 1.0f;
                } else {
                    r[s] = make_float4(0.f, 0.f, 0.f, 0.f);
                    dv[s] = 1.0f;
                }
            }
        }

        __syncthreads();
        const char* Ab = smem + buf * ASZ;

        float acc[4][4];
        #pragma unroll
        for (int nf = 0; nf < 4; nf++)
            #pragma unroll
            for (int j = 0; j < 4; j++) acc[nf][j] = 0.0f;

        #pragma unroll
        for (int ks = 0; ks < 16; ks++) {
            uint2 af0 = *(const uint2*)(Ab + a_base + ks * 32);
            uint2 af1 = *(const uint2*)(Ab + a_base + 8 * RSTR + ks * 32);
            #pragma unroll
            for (int nf = 0; nf < 4; nf++) {
                uint2 b = *(const uint2*)(Bs + b_base + nf * 8 * RSTR + ks * 32);
                mma_bf16(acc[nf], af0.x, af1.x, af0.y, af1.y, b.x, b.y);
            }
        }

        // epilogue: res*tanh + fp32 residual
        #pragma unroll
        for (int half = 0; half < 2; half++) {
            int row = row0 + warp_m * 16 + half * 8 + (lane >> 2);
            if (row < N) {
                #pragma unroll
                for (int nf = 0; nf < 4; nf++) {
                    int col = warp_n * 32 + nf * 8 + 2 * (lane & 3);
                    float v0 = acc[nf][half * 2 + 0];
                    float v1 = acc[nf][half * 2 + 1];
                    float2 b = *(const float2*)(xb + (size_t)row * D + col);
                    float2 o;
                    o.x = b.x + res * tanh_fast(v0);
                    o.y = b.y + res * tanh_fast(v1);
                    *(float2*)(out + (size_t)row * D + col) = o;
                }
            }
        }

        if (havenext) {
            char* An = smem + (buf ^ 1) * ASZ;
            #pragma unroll
            for (int s = 0; s < 8; s++) {
                float4 v = r[s];
                v.x *= dv[s]; v.y *= dv[s]; v.z *= dv[s]; v.w *= dv[s];
                store_bf16_quad(An + (m0 + 8 * s) * RSTR, kvt, v);
            }
        }
        buf ^= 1;
        row0 = next;
    }
}

// ---------------- launcher ------------------------------------------------
extern "C" void kernel_launch(void* const* d_in, const int* in_sizes, int n_in,
                              void* d_out, int out_size)
{
    const float* emb    = (const float*)d_in[0];
    const float* change = (const float*)d_in[1];
    const float* W1     = (const float*)d_in[2];
    const float* Wl1    = (const float*)d_in[3];
    const float* rel1   = (const float*)d_in[4];
    const float* W2     = (const float*)d_in[5];
    const float* Wl2    = (const float*)d_in[6];
    const float* rel2   = (const float*)d_in[7];
    const float* res    = (const float*)d_in[8];
    const float* jw     = (const float*)d_in[9];
    const float* ewj    = (const float*)d_in[10];
    const int*   ei     = (const int*)d_in[11];
    const int*   et     = (const int*)d_in[12];
    const int*   ej     = (const int*)d_in[13];

    const int N  = in_sizes[0] / D;
    const int E  = in_sizes[12];
    const int EJ = in_sizes[10];

    float* out = (float*)d_out;

    float *agg, *agg2, *h, *deg;
    char* wt;
    cudaGetSymbolAddress((void**)&agg,  g_agg);
    cudaGetSymbolAddress((void**)&agg2, g_agg2);
    cudaGetSymbolAddress((void**)&h,    g_h);
    cudaGetSymbolAddress((void**)&deg,  g_deg);
    cudaGetSymbolAddress((void**)&wt,   g_wt);

    cudaFuncSetAttribute(gemm_mma_kernel,
                         cudaFuncAttributeMaxDynamicSharedMemorySize, GEMM_SMEM);

    const size_t nd = (size_t)N * D * sizeof(float);

    prep_weights_kernel<<<2, 128>>>(W1, Wl1, W2, Wl2);
    cudaMemsetAsync(agg,  0, nd);
    cudaMemsetAsync(agg2, 0, nd);
    cudaMemsetAsync(deg,  0, (size_t)N * sizeof(float));
    cudaMemcpyAsync(out, change, nd, cudaMemcpyDeviceToDevice);

    const int eb = ((E + 3) / 4 + 7) / 8;      // 4 edges per warp, 8 warps/block
    const int jb = ((EJ + 3) / 4 + 7) / 8;

    scatter_kernel<<<eb, 256>>>(emb, rel1, ei, et, agg, deg, E);

    gemm_mma_kernel<<<148, NT, GEMM_SMEM>>>(
        agg, deg, emb, wt + 0 * 128 * RSTR, res, h, N);

    scatter_kernel<<<eb, 256>>>(h, rel2, ei, et, agg2, nullptr, E);

    gemm_mma_kernel<<<148, NT, GEMM_SMEM>>>(
        agg2, deg, h, wt + 1 * 128 * RSTR, res, out + (size_t)N * D, N);

    jump_kernel<<<jb, 256>>>(emb, ewj, ej, jw, out + (size_t)N * D, EJ);
}

// round 17
// speedup vs baseline: 1.2332x; 1.1558x over previous
#include <cuda_runtime.h>
#include <cstdint>
#include <cstddef>

#define D 128
#define NMAX 100000

// ---------------- static device scratch (no dynamic allocs allowed) -------
__device__ float g_agg[(size_t)NMAX * D];
__device__ float g_agg2[(size_t)NMAX * D];
__device__ float g_h[(size_t)NMAX * D];
__device__ float g_deg[NMAX];

#define RSTR 544                       // bytes per 256-k bf16 row (512 + 32 pad)
__device__ __align__(16) char g_wt[2][128 * RSTR];   // layer1: W1^T|Wl1^T, layer2: W2^T|Wl2^T

// ---------------- helpers -------------------------------------------------
__device__ __forceinline__ void red4(float* p, float4 v) {
    asm volatile("red.global.add.v4.f32 [%0], {%1,%2,%3,%4};"
                 :: "l"(p), "f"(v.x), "f"(v.y), "f"(v.z), "f"(v.w) : "memory");
}

__device__ __forceinline__ float tanh_fast(float x) {
    float y;
    asm("tanh.approx.f32 %0, %1;" : "=f"(y) : "f"(x));
    return y;
}

__device__ __forceinline__ uint32_t bf16x2(float lo, float hi) {
    uint32_t r;
    asm("cvt.rn.bf16x2.f32 %0, %1, %2;" : "=r"(r) : "f"(hi), "f"(lo));
    return r;
}

__device__ __forceinline__ void mma_bf16(float* c,
                                         uint32_t a0, uint32_t a1,
                                         uint32_t a2, uint32_t a3,
                                         uint32_t b0, uint32_t b1) {
    asm("mma.sync.aligned.m16n8k16.row.col.f32.bf16.bf16.f32 "
        "{%0,%1,%2,%3}, {%4,%5,%6,%7}, {%8,%9}, {%0,%1,%2,%3};"
        : "+f"(c[0]), "+f"(c[1]), "+f"(c[2]), "+f"(c[3])
        : "r"(a0), "r"(a1), "r"(a2), "r"(a3), "r"(b0), "r"(b1));
}

// Permuted-k bf16 quad store; valid for k % 4 == 0, k in [0, 256).
__device__ __forceinline__ void store_bf16_quad(char* rowbase, int k, float4 v) {
    char* p = rowbase + ((k >> 4) * 32) + (((k & 7) >> 1) * 8) + (((k >> 3) & 1) * 4);
    *(uint32_t*)p       = bf16x2(v.x, v.y);
    *(uint32_t*)(p + 8) = bf16x2(v.z, v.w);
}

// ---------------- prep: both layer weight pairs -> perm-k bf16 (once) -----
__global__ void prep_weights_kernel(const float* __restrict__ W1,
                                    const float* __restrict__ Wl1,
                                    const float* __restrict__ W2,
                                    const float* __restrict__ Wl2)
{
    const float* w  = blockIdx.x ? W2  : W1;
    const float* wl = blockIdx.x ? Wl2 : Wl1;
    const int n = threadIdx.x;
    char* brow = g_wt[blockIdx.x] + n * RSTR;
    #pragma unroll 4
    for (int k = 0; k < 128; k += 4) {
        float4 a, b;
        a.x = __ldg(w  + (k + 0) * 128 + n);
        a.y = __ldg(w  + (k + 1) * 128 + n);
        a.z = __ldg(w  + (k + 2) * 128 + n);
        a.w = __ldg(w  + (k + 3) * 128 + n);
        b.x = __ldg(wl + (k + 0) * 128 + n);
        b.y = __ldg(wl + (k + 1) * 128 + n);
        b.z = __ldg(wl + (k + 2) * 128 + n);
        b.w = __ldg(wl + (k + 3) * 128 + n);
        store_bf16_quad(brow, k, a);
        store_bf16_quad(brow, k + 128, b);
    }
}

// ---------------- invdeg: deg <- 1/max(deg,1) in place --------------------
__global__ void invdeg_kernel(float* __restrict__ deg, int N) {
    int i = blockIdx.x * blockDim.x + threadIdx.x;
    if (i < N) deg[i] = 1.0f / fmaxf(deg[i], 1.0f);
}

// ---------------- scatter: 4 edges per warp (4 independent chains) --------
// agg[dst] += x[src] * rel[etype]; deg count on layer 1.
__global__ void scatter_kernel(const float* __restrict__ x,
                               const float* __restrict__ rel,
                               const int* __restrict__ ei,     // [2, E]
                               const int* __restrict__ etype,  // [E]
                               float* __restrict__ agg,
                               float* __restrict__ deg,        // null on layer 2
                               int E)
{
    int w = blockIdx.x * (blockDim.x >> 5) + (threadIdx.x >> 5);
    int e0 = w * 4;
    if (e0 >= E) return;
    int lane = threadIdx.x & 31;

    int s[4], d[4], tt[4];
    bool has[4];
    #pragma unroll
    for (int i = 0; i < 4; i++) {
        int e = e0 + i;
        has[i] = e < E;
        s[i]  = has[i] ? __ldg(ei + e) : 0;
        d[i]  = has[i] ? __ldg(ei + E + e) : 0;
        tt[i] = has[i] ? __ldg(etype + e) : 0;
    }

    // 8 independent gather chains in flight
    float4 xv[4], rv[4];
    #pragma unroll
    for (int i = 0; i < 4; i++) {
        xv[i] = has[i] ? *(const float4*)(x + (size_t)s[i] * D + lane * 4)
                       : make_float4(0.f, 0.f, 0.f, 0.f);
        rv[i] = has[i] ? *(const float4*)(rel + (size_t)tt[i] * D + lane * 4)
                       : make_float4(0.f, 0.f, 0.f, 0.f);
    }

    #pragma unroll
    for (int i = 0; i < 4; i++) {
        if (!has[i]) break;
        float4 m;
        m.x = xv[i].x * rv[i].x; m.y = xv[i].y * rv[i].y;
        m.z = xv[i].z * rv[i].z; m.w = xv[i].w * rv[i].w;
        red4(agg + (size_t)d[i] * D + lane * 4, m);
    }
    if (deg != nullptr && lane == 0) {
        #pragma unroll
        for (int i = 0; i < 4; i++)
            if (has[i]) atomicAdd(deg + d[i], 1.0f);
    }
}

// ---------------- jump: 4 edges per warp ----------------------------------
__global__ void jump_kernel(const float* __restrict__ emb,
                            const float* __restrict__ ew,
                            const int* __restrict__ ej,   // [2, EJ]
                            const float* __restrict__ jw_p,
                            float* __restrict__ out,
                            int EJ)
{
    int w = blockIdx.x * (blockDim.x >> 5) + (threadIdx.x >> 5);
    int e0 = w * 4;
    if (e0 >= EJ) return;
    int lane = threadIdx.x & 31;
    const float jwv = __ldg(jw_p);

    int s[4], d[4];
    float wt[4];
    bool has[4];
    #pragma unroll
    for (int i = 0; i < 4; i++) {
        int e = e0 + i;
        has[i] = e < EJ;
        s[i]  = has[i] ? __ldg(ej + e) : 0;
        d[i]  = has[i] ? __ldg(ej + EJ + e) : 0;
        wt[i] = has[i] ? __ldg(ew + e) * jwv : 0.0f;
    }

    float4 xv[4];
    #pragma unroll
    for (int i = 0; i < 4; i++)
        xv[i] = has[i] ? *(const float4*)(emb + (size_t)s[i] * D + lane * 4)
                       : make_float4(0.f, 0.f, 0.f, 0.f);

    #pragma unroll
    for (int i = 0; i < 4; i++) {
        if (!has[i]) break;
        float4 m;
        m.x = xv[i].x * wt[i]; m.y = xv[i].y * wt[i];
        m.z = xv[i].z * wt[i]; m.w = xv[i].w * wt[i];
        red4(out + (size_t)d[i] * D + lane * 4, m);
    }
}

// ---------------- pipelined tensor-core GEMM (virtual K=256) --------------
// out[r] = xb[r] + res * tanh( agg[r]*invdeg[r] @ W + xb[r] @ Wl )
#define NT 512
#define ASZ (64 * RSTR)                    // 34816
#define GEMM_SMEM (2 * ASZ + 128 * RSTR)   // 139264 B

__global__ __launch_bounds__(NT, 1)
void gemm_mma_kernel(const float* __restrict__ agg,
                     const float* __restrict__ invdeg,
                     const float* __restrict__ xb,
                     const char* __restrict__ wt,     // prepped [128][RSTR]
                     const float* __restrict__ res_p,
                     float* __restrict__ out,
                     int N)
{
    extern __shared__ char smem[];
    char* Bs = smem + 2 * ASZ;

    const int t    = threadIdx.x;
    const int lane = t & 31;
    const int wid  = t >> 5;
    const int warp_m = wid & 3;      // 4 groups x 16 rows
    const int warp_n = wid >> 2;     // 4 groups x 32 cols

    for (int i = t * 16; i < 128 * RSTR; i += NT * 16)
        *(uint4*)(Bs + i) = *(const uint4*)(wt + i);
    const float res = __ldg(res_p);

    const int kvt = (t * 4) & 255;
    const int m0  = (t * 4) >> 8;            // 0..7
    const bool isagg = kvt < 128;
    const float* asrc = isagg ? agg : xb;
    const int koff = isagg ? kvt : kvt - 128;

    const int a_base = (warp_m * 16 + (lane >> 2)) * RSTR + (lane & 3) * 8;
    const int b_base = (warp_n * 32 + (lane >> 2)) * RSTR + (lane & 3) * 8;

    const int tile_step = gridDim.x * 64;
    int row0 = blockIdx.x * 64;
    if (row0 >= N) return;

    float4 r[8];
    float  dv[8];

    // prologue: load + store tile 0 into buffer 0
    #pragma unroll
    for (int s = 0; s < 8; s++) {
        int row = row0 + m0 + 8 * s;
        if (row < N) {
            r[s] = *(const float4*)(asrc + (size_t)row * D + koff);
            dv[s] = isagg ? __ldg(invdeg + row) : 1.0f;
        } else {
            r[s] = make_float4(0.f, 0.f, 0.f, 0.f);
            dv[s] = 1.0f;
        }
    }
    {
        char* Ab = smem;
        #pragma unroll
        for (int s = 0; s < 8; s++) {
            float4 v = r[s];
            v.x *= dv[s]; v.y *= dv[s]; v.z *= dv[s]; v.w *= dv[s];
            store_bf16_quad(Ab + (m0 + 8 * s) * RSTR, kvt, v);
        }
    }

    int buf = 0;
    for (; row0 < N; ) {
        const int next = row0 + tile_step;
        const bool havenext = next < N;

        // issue next tile's global loads (latency hidden behind mma below)
        if (havenext) {
            #pragma unroll
            for (int s = 0; s < 8; s++) {
                int row = next + m0 + 8 * s;
                if (row < N) {
                    r[s] = *(const float4*)(asrc + (size_t)row * D + koff);
                    dv[s] = isagg ? __ldg(invdeg + row) : 1.0f;
                } else {
                    r[s] = make_float4(0.f, 0.f, 0.f, 0.f);
                    dv[s] = 1.0f;
                }
            }
        }

        __syncthreads();
        const char* Ab = smem + buf * ASZ;

        float acc[4][4];
        #pragma unroll
        for (int nf = 0; nf < 4; nf++)
            #pragma unroll
            for (int j = 0; j < 4; j++) acc[nf][j] = 0.0f;

        #pragma unroll
        for (int ks = 0; ks < 16; ks++) {
            uint2 af0 = *(const uint2*)(Ab + a_base + ks * 32);
            uint2 af1 = *(const uint2*)(Ab + a_base + 8 * RSTR + ks * 32);
            #pragma unroll
            for (int nf = 0; nf < 4; nf++) {
                uint2 b = *(const uint2*)(Bs + b_base + nf * 8 * RSTR + ks * 32);
                mma_bf16(acc[nf], af0.x, af1.x, af0.y, af1.y, b.x, b.y);
            }
        }

        // epilogue: res*tanh + fp32 residual
        #pragma unroll
        for (int half = 0; half < 2; half++) {
            int row = row0 + warp_m * 16 + half * 8 + (lane >> 2);
            if (row < N) {
                #pragma unroll
                for (int nf = 0; nf < 4; nf++) {
                    int col = warp_n * 32 + nf * 8 + 2 * (lane & 3);
                    float v0 = acc[nf][half * 2 + 0];
                    float v1 = acc[nf][half * 2 + 1];
                    float2 b = *(const float2*)(xb + (size_t)row * D + col);
                    float2 o;
                    o.x = b.x + res * tanh_fast(v0);
                    o.y = b.y + res * tanh_fast(v1);
                    *(float2*)(out + (size_t)row * D + col) = o;
                }
            }
        }

        if (havenext) {
            char* An = smem + (buf ^ 1) * ASZ;
            #pragma unroll
            for (int s = 0; s < 8; s++) {
                float4 v = r[s];
                v.x *= dv[s]; v.y *= dv[s]; v.z *= dv[s]; v.w *= dv[s];
                store_bf16_quad(An + (m0 + 8 * s) * RSTR, kvt, v);
            }
        }
        buf ^= 1;
        row0 = next;
    }
}

// ---------------- launcher ------------------------------------------------
extern "C" void kernel_launch(void* const* d_in, const int* in_sizes, int n_in,
                              void* d_out, int out_size)
{
    const float* emb    = (const float*)d_in[0];
    const float* change = (const float*)d_in[1];
    const float* W1     = (const float*)d_in[2];
    const float* Wl1    = (const float*)d_in[3];
    const float* rel1   = (const float*)d_in[4];
    const float* W2     = (const float*)d_in[5];
    const float* Wl2    = (const float*)d_in[6];
    const float* rel2   = (const float*)d_in[7];
    const float* res    = (const float*)d_in[8];
    const float* jw     = (const float*)d_in[9];
    const float* ewj    = (const float*)d_in[10];
    const int*   ei     = (const int*)d_in[11];
    const int*   et     = (const int*)d_in[12];
    const int*   ej     = (const int*)d_in[13];

    const int N  = in_sizes[0] / D;
    const int E  = in_sizes[12];
    const int EJ = in_sizes[10];

    float* out = (float*)d_out;

    float *agg, *agg2, *h, *deg;
    char* wt;
    cudaGetSymbolAddress((void**)&agg,  g_agg);
    cudaGetSymbolAddress((void**)&agg2, g_agg2);
    cudaGetSymbolAddress((void**)&h,    g_h);
    cudaGetSymbolAddress((void**)&deg,  g_deg);
    cudaGetSymbolAddress((void**)&wt,   g_wt);

    cudaFuncSetAttribute(gemm_mma_kernel,
                         cudaFuncAttributeMaxDynamicSharedMemorySize, GEMM_SMEM);

    const size_t nd = (size_t)N * D * sizeof(float);

    prep_weights_kernel<<<2, 128>>>(W1, Wl1, W2, Wl2);
    cudaMemsetAsync(agg,  0, nd);
    cudaMemsetAsync(agg2, 0, nd);
    cudaMemsetAsync(deg,  0, (size_t)N * sizeof(float));
    cudaMemcpyAsync(out, change, nd, cudaMemcpyDeviceToDevice);

    const int eb = ((E + 3) / 4 + 7) / 8;      // 4 edges per warp, 8 warps/block
    const int jb = ((EJ + 3) / 4 + 7) / 8;

    scatter_kernel<<<eb, 256>>>(emb, rel1, ei, et, agg, deg, E);
    invdeg_kernel<<<(N + 1023) / 1024, 1024>>>(deg, N);

    gemm_mma_kernel<<<148, NT, GEMM_SMEM>>>(
        agg, deg, emb, wt + 0 * 128 * RSTR, res, h, N);

    scatter_kernel<<<eb, 256>>>(h, rel2, ei, et, agg2, nullptr, E);

    gemm_mma_kernel<<<148, NT, GEMM_SMEM>>>(
        agg2, deg, h, wt + 1 * 128 * RSTR, res, out + (size_t)N * D, N);

    jump_kernel<<<jb, 256>>>(emb, ewj, ej, jw, out + (size_t)N * D, EJ);
}